// round 7
// baseline (speedup 1.0000x reference)
#include <cuda_runtime.h>

#define B_ 2
#define F_ 128
#define N_ 192
#define S_ 192
#define H_ 4
#define D_ 64
#define HD_ 256
#define LOG2E 1.4426950408889634f

// SS[bh][i][s] = log2e*(s_src + q_src + b_attn), masked to -1e30 where A[s,i]==0
// SDT[bh][j][s] = log2e*(s_dst + q_dst)   (j-major for coalesced column reads)
static __device__ __align__(16) float d_SS [B_*H_*N_*S_];
static __device__ __align__(16) float d_SDT[B_*H_*N_*S_];
static __device__ float d_P[F_*8];
static __device__ float d_Q[8];
static __device__ float d_colsum2[B_*F_*2];
static __device__ float d_sumg[HD_];

__device__ __forceinline__ float ex2f(float x){ float r; asm("ex2.approx.ftz.f32 %0, %1;" : "=f"(r) : "f"(x)); return r; }
__device__ __forceinline__ float rcpf(float x){ float r; asm("rcp.approx.ftz.f32 %0, %1;" : "=f"(r) : "f"(x)); return r; }

// ---- launch 1: fold W_attn into W_lin/b_lin (tiny) ----
__global__ void k_prep(const float* __restrict__ Wl, const float* __restrict__ bl,
                       const float* __restrict__ Wa, const float* __restrict__ ba){
    int t = threadIdx.x;
    if (t < 512){
        int f = t >> 2, h = t & 3;
        float ps = 0.f, pd = 0.f;
        #pragma unroll 8
        for (int d = 0; d < D_; ++d){
            float wl = Wl[f*HD_ + h*D_ + d];
            ps += wl * Wa[d];
            pd += wl * Wa[D_ + d];
        }
        d_P[f*8 + h]     = ps * LOG2E;
        d_P[f*8 + 4 + h] = pd * LOG2E;
    }
    if (t < 8){
        int which = t >> 2, h = t & 3;
        float q = 0.f;
        for (int d = 0; d < D_; ++d) q += bl[h*D_ + d] * Wa[which*D_ + d];
        if (which == 0) q += ba[0];
        d_Q[which*4 + h] = q * LOG2E;
    }
}

// ---- launch 2: proj (blocks 0..383) + colsum halves (blocks 384..895) ----
__global__ void __launch_bounds__(192) k_main(const float* __restrict__ X,
                                              const int* __restrict__ A){
    int t = threadIdx.x;
    if (blockIdx.x >= 384){
        int cb   = blockIdx.x - 384;      // 512 half-slices
        int bf   = cb >> 1;
        int half = cb & 1;
        const float4* p = (const float4*)(X + (size_t)bf*(N_*S_) + half*(N_*S_/2));
        float acc = 0.f;
        #pragma unroll 4
        for (int i = t; i < (N_*S_)/8; i += 192){
            float4 v = __ldg(p + i);
            acc += (v.x + v.y) + (v.z + v.w);
        }
        unsigned m = 0xFFFFFFFFu;
        acc += __shfl_down_sync(m, acc, 16);
        acc += __shfl_down_sync(m, acc, 8);
        acc += __shfl_down_sync(m, acc, 4);
        acc += __shfl_down_sync(m, acc, 2);
        acc += __shfl_down_sync(m, acc, 1);
        __shared__ float wparts[6];
        if ((t & 31) == 0) wparts[t >> 5] = acc;
        __syncthreads();
        if (t == 0)
            d_colsum2[cb] = ((wparts[0]+wparts[1]) + (wparts[2]+wparts[3])) + (wparts[4]+wparts[5]);
        return;
    }
    // projection: 128->8 GEMV per (b,n,s=t), MLP-16 batches
    __shared__ float sP[F_*8];
    __shared__ float sQ[8];
    int b = blockIdx.x / N_, n = blockIdx.x % N_;
    for (int i = t; i < F_*8; i += 192) sP[i] = d_P[i];
    if (t < 8) sQ[t] = d_Q[t];
    __syncthreads();
    float acc[8];
    #pragma unroll
    for (int k = 0; k < 8; ++k) acc[k] = 0.f;
    const float* xp = X + ((size_t)(b*F_)*N_ + n)*S_ + t;
    #pragma unroll
    for (int f0 = 0; f0 < F_; f0 += 16){
        float xv[16];
        #pragma unroll
        for (int k = 0; k < 16; ++k) xv[k] = __ldg(xp + (size_t)(f0+k)*(N_*S_));
        #pragma unroll
        for (int k = 0; k < 16; ++k){
            float4 p0 = ((const float4*)sP)[(f0+k)*2];
            float4 p1 = ((const float4*)sP)[(f0+k)*2 + 1];
            acc[0] += xv[k]*p0.x; acc[1] += xv[k]*p0.y; acc[2] += xv[k]*p0.z; acc[3] += xv[k]*p0.w;
            acc[4] += xv[k]*p1.x; acc[5] += xv[k]*p1.y; acc[6] += xv[k]*p1.z; acc[7] += xv[k]*p1.w;
        }
    }
    int av = A[t*N_ + n];   // mask A[s=t, i=n]
    #pragma unroll
    for (int h = 0; h < H_; ++h){
        int bh = b*H_ + h;
        float u = acc[h] + sQ[h];
        d_SS [((size_t)bh*N_ + n)*S_ + t] = av ? u : -1e30f;
        d_SDT[((size_t)bh*N_ + n)*S_ + t] = acc[4+h] + sQ[4+h];   // [bh][j=n][s]
    }
}

// ---- launch 3: sum_g[c] = colsumX · W_lin[:,c] + R*b_lin[c] ----
__global__ void __launch_bounds__(256) k_sumg(const float* __restrict__ Wl,
                                              const float* __restrict__ bl){
    __shared__ float cs[F_];
    int t = threadIdx.x;
    if (t < F_)
        cs[t] = (d_colsum2[2*t] + d_colsum2[2*t+1])
              + (d_colsum2[2*F_ + 2*t] + d_colsum2[2*F_ + 2*t+1]);
    __syncthreads();
    float acc = (float)(B_*N_*S_) * bl[t];
    #pragma unroll
    for (int f0 = 0; f0 < F_; f0 += 16){
        float wv[16];
        #pragma unroll
        for (int k = 0; k < 16; ++k) wv[k] = Wl[(f0+k)*HD_ + t];
        #pragma unroll
        for (int k = 0; k < 16; ++k) acc += cs[f0+k] * wv[k];
    }
    d_sumg[t] = acc;
}

// ---- launch 4: attention, one CTA per (b,h, i-pair); warp owns 32 columns j ----
// lane s-map: {4l..4l+3} and {128+2l, 128+2l+1}
__global__ void __launch_bounds__(192) k_attn(float* __restrict__ out){
    __shared__ float w0[S_], w1[S_];
    __shared__ float AL[6][2][S_];
    __shared__ float sg[D_];

    int i0 = blockIdx.x * 2, h = blockIdx.y, b = blockIdx.z;
    int bh = b*H_ + h;
    int t  = threadIdx.x, lane = t & 31, wp = t >> 5;

    w0[t] = d_SS[((size_t)bh*N_ + i0    )*S_ + t];
    w1[t] = d_SS[((size_t)bh*N_ + i0 + 1)*S_ + t];
    if (t < D_) sg[t] = d_sumg[h*D_ + t];
    __syncthreads();

    float wr0[6], wr1[6], acc0[6], acc1[6];
    {
        float4 a4 = *(const float4*)(w0 + 4*lane);
        float2 a2 = *(const float2*)(w0 + 128 + 2*lane);
        wr0[0]=a4.x; wr0[1]=a4.y; wr0[2]=a4.z; wr0[3]=a4.w; wr0[4]=a2.x; wr0[5]=a2.y;
        float4 b4 = *(const float4*)(w1 + 4*lane);
        float2 b2 = *(const float2*)(w1 + 128 + 2*lane);
        wr1[0]=b4.x; wr1[1]=b4.y; wr1[2]=b4.z; wr1[3]=b4.w; wr1[4]=b2.x; wr1[5]=b2.y;
    }
    #pragma unroll
    for (int k = 0; k < 6; ++k){ acc0[k] = 0.f; acc1[k] = 0.f; }

    const float* VT = d_SDT + (size_t)bh*N_*S_;
    const unsigned m = 0xFFFFFFFFu;

    #pragma unroll 2
    for (int jj = 0; jj < 32; ++jj){
        const float* vrow = VT + (size_t)(wp*32 + jj)*S_;
        float4 v4 = __ldg((const float4*)(vrow + 4*lane));
        float2 v2 = __ldg((const float2*)(vrow + 128 + 2*lane));
        float vr[6] = {v4.x, v4.y, v4.z, v4.w, v2.x, v2.y};
        float e0[6], e1[6];
        float z0 = 0.f, z1 = 0.f;
        #pragma unroll
        for (int k = 0; k < 6; ++k){
            float a = wr0[k] + vr[k];
            e0[k] = ex2f(fmaxf(a, 0.2f*a));
            z0 += e0[k];
            float c = wr1[k] + vr[k];
            e1[k] = ex2f(fmaxf(c, 0.2f*c));
            z1 += e1[k];
        }
        // two independent shuffle chains — interleaved by the scheduler
        z0 += __shfl_xor_sync(m, z0, 16);  z1 += __shfl_xor_sync(m, z1, 16);
        z0 += __shfl_xor_sync(m, z0, 8);   z1 += __shfl_xor_sync(m, z1, 8);
        z0 += __shfl_xor_sync(m, z0, 4);   z1 += __shfl_xor_sync(m, z1, 4);
        z0 += __shfl_xor_sync(m, z0, 2);   z1 += __shfl_xor_sync(m, z1, 2);
        z0 += __shfl_xor_sync(m, z0, 1);   z1 += __shfl_xor_sync(m, z1, 1);
        float iz0 = (z0 > 0.f) ? rcpf(z0) : 0.f;
        float iz1 = (z1 > 0.f) ? rcpf(z1) : 0.f;
        #pragma unroll
        for (int k = 0; k < 6; ++k){
            acc0[k] += e0[k]*iz0;
            acc1[k] += e1[k]*iz1;
        }
    }

    // per-warp alpha partials
    #pragma unroll
    for (int k = 0; k < 4; ++k){
        AL[wp][0][4*lane+k] = acc0[k];
        AL[wp][1][4*lane+k] = acc1[k];
    }
    AL[wp][0][128+2*lane]   = acc0[4];
    AL[wp][0][128+2*lane+1] = acc0[5];
    AL[wp][1][128+2*lane]   = acc1[4];
    AL[wp][1][128+2*lane+1] = acc1[5];
    __syncthreads();
    // final alphas into w0/w1 (no longer needed)
    w0[t] = ((AL[0][0][t]+AL[1][0][t]) + (AL[2][0][t]+AL[3][0][t])) + (AL[4][0][t]+AL[5][0][t]);
    w1[t] = ((AL[0][1][t]+AL[1][1][t]) + (AL[2][1][t]+AL[3][1][t])) + (AL[4][1][t]+AL[5][1][t]);
    __syncthreads();

    // output: alpha_i[s] * sum_g[d], float4 along s, both i's
    for (int idx = t; idx < 2*D_*(S_/4); idx += 192){
        int ii = idx / (D_*(S_/4));
        int r  = idx % (D_*(S_/4));
        int d  = r / (S_/4);
        int s4 = r % (S_/4);
        const float* ALp = ii ? w1 : w0;
        float4 a4 = *(const float4*)(ALp + s4*4);
        float sv = sg[d];
        float4 o = make_float4(a4.x*sv, a4.y*sv, a4.z*sv, a4.w*sv);
        *(float4*)(out + ((size_t)(b*HD_ + h*D_ + d)*N_ + i0 + ii)*S_ + s4*4) = o;
    }
}

extern "C" void kernel_launch(void* const* d_in, const int* in_sizes, int n_in,
                              void* d_out, int out_size){
    const float* X  = (const float*)d_in[0];
    const int*   A  = (const int*)  d_in[1];
    const float* Wl = (const float*)d_in[2];
    const float* bl = (const float*)d_in[3];
    const float* Wa = (const float*)d_in[4];
    const float* ba = (const float*)d_in[5];
    float* out = (float*)d_out;

    k_prep <<<1, 512>>>(Wl, bl, Wa, ba);
    k_main <<<896, 192>>>(X, A);
    k_sumg <<<1, HD_>>>(Wl, bl);
    dim3 g(N_/2, H_, B_);
    k_attn <<<g, 192>>>(out);
}

// round 8
// speedup vs baseline: 1.1240x; 1.1240x over previous
#include <cuda_runtime.h>

#define B_ 2
#define F_ 128
#define N_ 192
#define S_ 192
#define H_ 4
#define D_ 64
#define HD_ 256
#define LOG2E 1.4426950408889634f

// SS[bh][i][s] = log2e*(s_src + q_src + b_attn), masked to -1e30 where A[s,i]==0
// SDT[bh][j][s] = log2e*(s_dst + q_dst)   (j-major for coalesced column reads)
static __device__ __align__(16) float d_SS [B_*H_*N_*S_];
static __device__ __align__(16) float d_SDT[B_*H_*N_*S_];
static __device__ float d_P[F_*8];
static __device__ float d_Q[8];
static __device__ float d_colsum2[B_*F_*2];
static __device__ float d_sumg[HD_];

__device__ __forceinline__ float ex2f(float x){ float r; asm("ex2.approx.ftz.f32 %0, %1;" : "=f"(r) : "f"(x)); return r; }
__device__ __forceinline__ float rcpf(float x){ float r; asm("rcp.approx.ftz.f32 %0, %1;" : "=f"(r) : "f"(x)); return r; }

// ---- launch 1: colsum half-slices (independent of everything else) ----
__global__ void __launch_bounds__(256) k_colsum(const float* __restrict__ X){
    int cb   = blockIdx.x;            // 512 half-slices
    int bf   = cb >> 1;
    int half = cb & 1;
    const float4* p = (const float4*)(X + (size_t)bf*(N_*S_) + half*(N_*S_/2));
    float acc = 0.f;
    #pragma unroll 6
    for (int i = threadIdx.x; i < (N_*S_)/8; i += 256){
        float4 v = __ldg(p + i);
        acc += (v.x + v.y) + (v.z + v.w);
    }
    unsigned m = 0xFFFFFFFFu;
    acc += __shfl_down_sync(m, acc, 16);
    acc += __shfl_down_sync(m, acc, 8);
    acc += __shfl_down_sync(m, acc, 4);
    acc += __shfl_down_sync(m, acc, 2);
    acc += __shfl_down_sync(m, acc, 1);
    __shared__ float wparts[8];
    if ((threadIdx.x & 31) == 0) wparts[threadIdx.x >> 5] = acc;
    __syncthreads();
    if (threadIdx.x == 0){
        float s = 0.f;
        #pragma unroll
        for (int k = 0; k < 8; ++k) s += wparts[k];
        d_colsum2[cb] = s;
    }
}

// ---- launch 2: fold W_attn into W_lin/b_lin; 4 blocks over f ----
__global__ void __launch_bounds__(128) k_prep(const float* __restrict__ Wl, const float* __restrict__ bl,
                                              const float* __restrict__ Wa, const float* __restrict__ ba){
    int t = threadIdx.x;
    int f = blockIdx.x*32 + (t >> 2), h = t & 3;
    float ps = 0.f, pd = 0.f;
    #pragma unroll 8
    for (int d = 0; d < D_; ++d){
        float wl = Wl[f*HD_ + h*D_ + d];
        ps += wl * Wa[d];
        pd += wl * Wa[D_ + d];
    }
    d_P[f*8 + h]     = ps * LOG2E;
    d_P[f*8 + 4 + h] = pd * LOG2E;
    if (blockIdx.x == 0 && t < 8){
        int which = t >> 2, hh = t & 3;
        float q = 0.f;
        for (int d = 0; d < D_; ++d) q += bl[hh*D_ + d] * Wa[which*D_ + d];
        if (which == 0) q += ba[0];
        d_Q[which*4 + hh] = q * LOG2E;
    }
}

// ---- launch 3: sum_g[c] = colsumX · W_lin[:,c] + R*b_lin[c] ----
__global__ void __launch_bounds__(256) k_sumg(const float* __restrict__ Wl,
                                              const float* __restrict__ bl){
    __shared__ float cs[F_];
    int t = threadIdx.x;
    if (t < F_)
        cs[t] = (d_colsum2[2*t] + d_colsum2[2*t+1])
              + (d_colsum2[2*F_ + 2*t] + d_colsum2[2*F_ + 2*t+1]);
    __syncthreads();
    float acc = (float)(B_*N_*S_) * bl[t];
    #pragma unroll
    for (int f0 = 0; f0 < F_; f0 += 16){
        float wv[16];
        #pragma unroll
        for (int k = 0; k < 16; ++k) wv[k] = Wl[(f0+k)*HD_ + t];
        #pragma unroll
        for (int k = 0; k < 16; ++k) acc += cs[f0+k] * wv[k];
    }
    d_sumg[t] = acc;
}

// ---- launch 4: projection, f-reduction split over two thread halves ----
__global__ void __launch_bounds__(384) k_proj(const float* __restrict__ X,
                                              const int* __restrict__ A){
    __shared__ float sP[F_*8];
    __shared__ float sQ[8];
    __shared__ float pacc[192][9];   // pad 9 -> conflict-free scalar access
    int b = blockIdx.x / N_, n = blockIdx.x % N_;
    int t = threadIdx.x;
    for (int i = t; i < F_*8; i += 384) sP[i] = d_P[i];
    if (t < 8) sQ[t] = d_Q[t];
    __syncthreads();
    int s  = (t < 192) ? t : t - 192;
    int fb = (t < 192) ? 0 : 64;
    float acc[8];
    #pragma unroll
    for (int k = 0; k < 8; ++k) acc[k] = 0.f;
    const float* xp = X + ((size_t)(b*F_ + fb)*N_ + n)*S_ + s;
    #pragma unroll
    for (int f0 = 0; f0 < 64; f0 += 16){
        float xv[16];
        #pragma unroll
        for (int k = 0; k < 16; ++k) xv[k] = __ldg(xp + (size_t)(f0+k)*(N_*S_));
        #pragma unroll
        for (int k = 0; k < 16; ++k){
            const float* pr = sP + (fb+f0+k)*8;
            float4 p0 = *(const float4*)pr;
            float4 p1 = *(const float4*)(pr+4);
            acc[0] += xv[k]*p0.x; acc[1] += xv[k]*p0.y; acc[2] += xv[k]*p0.z; acc[3] += xv[k]*p0.w;
            acc[4] += xv[k]*p1.x; acc[5] += xv[k]*p1.y; acc[6] += xv[k]*p1.z; acc[7] += xv[k]*p1.w;
        }
    }
    if (t >= 192){
        #pragma unroll
        for (int k = 0; k < 8; ++k) pacc[s][k] = acc[k];
    }
    __syncthreads();
    if (t < 192){
        #pragma unroll
        for (int k = 0; k < 8; ++k) acc[k] += pacc[s][k];
        int av = A[s*N_ + n];   // mask A[s, i=n]
        #pragma unroll
        for (int h = 0; h < H_; ++h){
            int bh = b*H_ + h;
            float u = acc[h] + sQ[h];
            d_SS [((size_t)bh*N_ + n)*S_ + s] = av ? u : -1e30f;
            d_SDT[((size_t)bh*N_ + n)*S_ + s] = acc[4+h] + sQ[4+h];
        }
    }
}

// ---- launch 5: attention, one CTA per (b,h, i-pair); warp owns 32 columns j ----
// lane s-map: {4l..4l+3} and {128+2l, 128+2l+1}
__global__ void __launch_bounds__(192) k_attn(float* __restrict__ out){
    __shared__ float w0[S_], w1[S_];
    __shared__ float AL[6][2][S_];
    __shared__ float sg[D_];

    int i0 = blockIdx.x * 2, h = blockIdx.y, b = blockIdx.z;
    int bh = b*H_ + h;
    int t  = threadIdx.x, lane = t & 31, wp = t >> 5;

    w0[t] = d_SS[((size_t)bh*N_ + i0    )*S_ + t];
    w1[t] = d_SS[((size_t)bh*N_ + i0 + 1)*S_ + t];
    if (t < D_) sg[t] = d_sumg[h*D_ + t];
    __syncthreads();

    float wr0[6], wr1[6], acc0[6], acc1[6];
    {
        float4 a4 = *(const float4*)(w0 + 4*lane);
        float2 a2 = *(const float2*)(w0 + 128 + 2*lane);
        wr0[0]=a4.x; wr0[1]=a4.y; wr0[2]=a4.z; wr0[3]=a4.w; wr0[4]=a2.x; wr0[5]=a2.y;
        float4 b4 = *(const float4*)(w1 + 4*lane);
        float2 b2 = *(const float2*)(w1 + 128 + 2*lane);
        wr1[0]=b4.x; wr1[1]=b4.y; wr1[2]=b4.z; wr1[3]=b4.w; wr1[4]=b2.x; wr1[5]=b2.y;
    }
    #pragma unroll
    for (int k = 0; k < 6; ++k){ acc0[k] = 0.f; acc1[k] = 0.f; }

    const float* VT = d_SDT + (size_t)bh*N_*S_;
    const unsigned m = 0xFFFFFFFFu;

    #pragma unroll 2
    for (int jj = 0; jj < 32; ++jj){
        const float* vrow = VT + (size_t)(wp*32 + jj)*S_;
        float4 v4 = __ldg((const float4*)(vrow + 4*lane));
        float2 v2 = __ldg((const float2*)(vrow + 128 + 2*lane));
        float vr[6] = {v4.x, v4.y, v4.z, v4.w, v2.x, v2.y};
        float e0[6], e1[6];
        float z0 = 0.f, z1 = 0.f;
        #pragma unroll
        for (int k = 0; k < 6; ++k){
            float a = wr0[k] + vr[k];
            e0[k] = ex2f(fmaxf(a, 0.2f*a));
            z0 += e0[k];
            float c = wr1[k] + vr[k];
            e1[k] = ex2f(fmaxf(c, 0.2f*c));
            z1 += e1[k];
        }
        z0 += __shfl_xor_sync(m, z0, 16);  z1 += __shfl_xor_sync(m, z1, 16);
        z0 += __shfl_xor_sync(m, z0, 8);   z1 += __shfl_xor_sync(m, z1, 8);
        z0 += __shfl_xor_sync(m, z0, 4);   z1 += __shfl_xor_sync(m, z1, 4);
        z0 += __shfl_xor_sync(m, z0, 2);   z1 += __shfl_xor_sync(m, z1, 2);
        z0 += __shfl_xor_sync(m, z0, 1);   z1 += __shfl_xor_sync(m, z1, 1);
        float iz0 = (z0 > 0.f) ? rcpf(z0) : 0.f;
        float iz1 = (z1 > 0.f) ? rcpf(z1) : 0.f;
        #pragma unroll
        for (int k = 0; k < 6; ++k){
            acc0[k] += e0[k]*iz0;
            acc1[k] += e1[k]*iz1;
        }
    }

    #pragma unroll
    for (int k = 0; k < 4; ++k){
        AL[wp][0][4*lane+k] = acc0[k];
        AL[wp][1][4*lane+k] = acc1[k];
    }
    AL[wp][0][128+2*lane]   = acc0[4];
    AL[wp][0][128+2*lane+1] = acc0[5];
    AL[wp][1][128+2*lane]   = acc1[4];
    AL[wp][1][128+2*lane+1] = acc1[5];
    __syncthreads();
    w0[t] = ((AL[0][0][t]+AL[1][0][t]) + (AL[2][0][t]+AL[3][0][t])) + (AL[4][0][t]+AL[5][0][t]);
    w1[t] = ((AL[0][1][t]+AL[1][1][t]) + (AL[2][1][t]+AL[3][1][t])) + (AL[4][1][t]+AL[5][1][t]);
    __syncthreads();

    for (int idx = t; idx < 2*D_*(S_/4); idx += 192){
        int ii = idx / (D_*(S_/4));
        int r  = idx % (D_*(S_/4));
        int d  = r / (S_/4);
        int s4 = r % (S_/4);
        const float* ALp = ii ? w1 : w0;
        float4 a4 = *(const float4*)(ALp + s4*4);
        float sv = sg[d];
        float4 o = make_float4(a4.x*sv, a4.y*sv, a4.z*sv, a4.w*sv);
        *(float4*)(out + ((size_t)(b*HD_ + h*D_ + d)*N_ + i0 + ii)*S_ + s4*4) = o;
    }
}

extern "C" void kernel_launch(void* const* d_in, const int* in_sizes, int n_in,
                              void* d_out, int out_size){
    const float* X  = (const float*)d_in[0];
    const int*   A  = (const int*)  d_in[1];
    const float* Wl = (const float*)d_in[2];
    const float* bl = (const float*)d_in[3];
    const float* Wa = (const float*)d_in[4];
    const float* ba = (const float*)d_in[5];
    float* out = (float*)d_out;

    k_colsum<<<512, 256>>>(X);
    k_prep  <<<4, 128>>>(Wl, bl, Wa, ba);
    k_sumg  <<<1, HD_>>>(Wl, bl);
    k_proj  <<<B_*N_, 384>>>(X, A);
    dim3 g(N_/2, H_, B_);
    k_attn  <<<g, 192>>>(out);
}

// round 9
// speedup vs baseline: 1.1940x; 1.0623x over previous
#include <cuda_runtime.h>

#define B_ 2
#define F_ 128
#define N_ 192
#define S_ 192
#define H_ 4
#define D_ 64
#define HD_ 256
#define LOG2E 1.4426950408889634f

// SS[bh][i][s] = log2e*(s_src + q_src + b_attn), masked to -1e30 where A[s,i]==0
// SDT[bh][j][s] = log2e*(s_dst + q_dst)   (j-major for coalesced column reads)
static __device__ __align__(16) float d_SS [B_*H_*N_*S_];
static __device__ __align__(16) float d_SDT[B_*H_*N_*S_];
static __device__ float d_P[F_*8];
static __device__ float d_Q[8];
static __device__ float d_colsum2[B_*F_*2];

__device__ __forceinline__ float ex2f(float x){ float r; asm("ex2.approx.ftz.f32 %0, %1;" : "=f"(r) : "f"(x)); return r; }
__device__ __forceinline__ float rcpf(float x){ float r; asm("rcp.approx.ftz.f32 %0, %1;" : "=f"(r) : "f"(x)); return r; }

// ---- launch 1: colsum half-slices ----
__global__ void __launch_bounds__(256) k_colsum(const float* __restrict__ X){
    int cb   = blockIdx.x;            // 512 half-slices
    int bf   = cb >> 1;
    int half = cb & 1;
    const float4* p = (const float4*)(X + (size_t)bf*(N_*S_) + half*(N_*S_/2));
    float acc = 0.f;
    #pragma unroll 6
    for (int i = threadIdx.x; i < (N_*S_)/8; i += 256){
        float4 v = __ldg(p + i);
        acc += (v.x + v.y) + (v.z + v.w);
    }
    unsigned m = 0xFFFFFFFFu;
    acc += __shfl_down_sync(m, acc, 16);
    acc += __shfl_down_sync(m, acc, 8);
    acc += __shfl_down_sync(m, acc, 4);
    acc += __shfl_down_sync(m, acc, 2);
    acc += __shfl_down_sync(m, acc, 1);
    __shared__ float wparts[8];
    if ((threadIdx.x & 31) == 0) wparts[threadIdx.x >> 5] = acc;
    __syncthreads();
    if (threadIdx.x == 0){
        float s = 0.f;
        #pragma unroll
        for (int k = 0; k < 8; ++k) s += wparts[k];
        d_colsum2[cb] = s;
    }
}

// ---- launch 2: fold W_attn into W_lin/b_lin; 4 blocks over f ----
__global__ void __launch_bounds__(128) k_prep(const float* __restrict__ Wl, const float* __restrict__ bl,
                                              const float* __restrict__ Wa, const float* __restrict__ ba){
    int t = threadIdx.x;
    int f = blockIdx.x*32 + (t >> 2), h = t & 3;
    float ps = 0.f, pd = 0.f;
    #pragma unroll 8
    for (int d = 0; d < D_; ++d){
        float wl = Wl[f*HD_ + h*D_ + d];
        ps += wl * Wa[d];
        pd += wl * Wa[D_ + d];
    }
    d_P[f*8 + h]     = ps * LOG2E;
    d_P[f*8 + 4 + h] = pd * LOG2E;
    if (blockIdx.x == 0 && t < 8){
        int which = t >> 2, hh = t & 3;
        float q = 0.f;
        for (int d = 0; d < D_; ++d) q += bl[hh*D_ + d] * Wa[which*D_ + d];
        if (which == 0) q += ba[0];
        d_Q[which*4 + hh] = q * LOG2E;
    }
}

// ---- launch 3: projection; block = (b, n, s-half), 4 f-quarter groups x 96 s ----
__global__ void __launch_bounds__(384, 4) k_proj(const float* __restrict__ X,
                                                 const int* __restrict__ A){
    __shared__ float sP[F_*8];
    __shared__ float sQ[8];
    __shared__ float pacc[3][96][9];
    int blk = blockIdx.x;
    int b  = blk / (N_*2);
    int r  = blk % (N_*2);
    int n  = r >> 1;
    int sh = r & 1;
    int t  = threadIdx.x;
    for (int i = t; i < F_*8; i += 384) sP[i] = d_P[i];
    if (t < 8) sQ[t] = d_Q[t];
    __syncthreads();
    int sl = t % 96;
    int fg = t / 96;
    int s  = sh*96 + sl;
    int fb = fg*32;
    float acc[8];
    #pragma unroll
    for (int k = 0; k < 8; ++k) acc[k] = 0.f;
    const float* xp = X + ((size_t)(b*F_ + fb)*N_ + n)*S_ + s;
    #pragma unroll
    for (int f0 = 0; f0 < 32; f0 += 16){
        float xv[16];
        #pragma unroll
        for (int k = 0; k < 16; ++k) xv[k] = __ldg(xp + (size_t)(f0+k)*(N_*S_));
        #pragma unroll
        for (int k = 0; k < 16; ++k){
            const float* pr = sP + (fb+f0+k)*8;
            float4 p0 = *(const float4*)pr;
            float4 p1 = *(const float4*)(pr+4);
            acc[0] += xv[k]*p0.x; acc[1] += xv[k]*p0.y; acc[2] += xv[k]*p0.z; acc[3] += xv[k]*p0.w;
            acc[4] += xv[k]*p1.x; acc[5] += xv[k]*p1.y; acc[6] += xv[k]*p1.z; acc[7] += xv[k]*p1.w;
        }
    }
    if (fg > 0){
        #pragma unroll
        for (int k = 0; k < 8; ++k) pacc[fg-1][sl][k] = acc[k];
    }
    __syncthreads();
    if (fg == 0){
        #pragma unroll
        for (int g = 0; g < 3; ++g)
            #pragma unroll
            for (int k = 0; k < 8; ++k) acc[k] += pacc[g][sl][k];
        int av = A[s*N_ + n];   // mask A[s, i=n]
        #pragma unroll
        for (int h = 0; h < H_; ++h){
            int bh = b*H_ + h;
            float u = acc[h] + sQ[h];
            d_SS [((size_t)bh*N_ + n)*S_ + s] = av ? u : -1e30f;
            d_SDT[((size_t)bh*N_ + n)*S_ + s] = acc[4+h] + sQ[4+h];
        }
    }
}

// ---- launch 4: attention (+ inline sum_g); one CTA per (b,h,i-pair) ----
// lane s-map: {4l..4l+3} and {128+2l, 128+2l+1}
__global__ void __launch_bounds__(192, 6) k_attn(const float* __restrict__ Wl,
                                                 const float* __restrict__ bl,
                                                 float* __restrict__ out){
    __shared__ float w0[S_], w1[S_];
    __shared__ float AL[6][2][S_];
    __shared__ float sg[D_];
    __shared__ float cs[F_];

    int i0 = blockIdx.x * 2, h = blockIdx.y, b = blockIdx.z;
    int bh = b*H_ + h;
    int t  = threadIdx.x, lane = t & 31, wp = t >> 5;

    w0[t] = d_SS[((size_t)bh*N_ + i0    )*S_ + t];
    w1[t] = d_SS[((size_t)bh*N_ + i0 + 1)*S_ + t];
    if (t < F_)
        cs[t] = (d_colsum2[2*t] + d_colsum2[2*t+1])
              + (d_colsum2[2*F_ + 2*t] + d_colsum2[2*F_ + 2*t+1]);
    __syncthreads();

    // inline sum_g for this head: sg[d] = R*bl[c] + sum_f cs[f]*Wl[f,c]
    if (t < D_){
        int c = h*D_ + t;
        float acc = (float)(B_*N_*S_) * __ldg(bl + c);
        #pragma unroll
        for (int f0 = 0; f0 < F_; f0 += 16){
            float wv[16];
            #pragma unroll
            for (int k = 0; k < 16; ++k) wv[k] = __ldg(Wl + (f0+k)*HD_ + c);
            #pragma unroll
            for (int k = 0; k < 16; ++k) acc += cs[f0+k] * wv[k];
        }
        sg[t] = acc;    // visible to all after the post-mainloop barrier
    }

    float wr0[6], wr1[6], acc0[6], acc1[6];
    {
        float4 a4 = *(const float4*)(w0 + 4*lane);
        float2 a2 = *(const float2*)(w0 + 128 + 2*lane);
        wr0[0]=a4.x; wr0[1]=a4.y; wr0[2]=a4.z; wr0[3]=a4.w; wr0[4]=a2.x; wr0[5]=a2.y;
        float4 b4 = *(const float4*)(w1 + 4*lane);
        float2 b2 = *(const float2*)(w1 + 128 + 2*lane);
        wr1[0]=b4.x; wr1[1]=b4.y; wr1[2]=b4.z; wr1[3]=b4.w; wr1[4]=b2.x; wr1[5]=b2.y;
    }
    #pragma unroll
    for (int k = 0; k < 6; ++k){ acc0[k] = 0.f; acc1[k] = 0.f; }

    const float* VT = d_SDT + (size_t)bh*N_*S_;
    const unsigned m = 0xFFFFFFFFu;

    #pragma unroll 4
    for (int jj = 0; jj < 32; ++jj){
        const float* vrow = VT + (size_t)(wp*32 + jj)*S_;
        float4 v4 = __ldg((const float4*)(vrow + 4*lane));
        float2 v2 = __ldg((const float2*)(vrow + 128 + 2*lane));
        float vr[6] = {v4.x, v4.y, v4.z, v4.w, v2.x, v2.y};
        float e0[6], e1[6];
        float z0 = 0.f, z1 = 0.f;
        #pragma unroll
        for (int k = 0; k < 6; ++k){
            float a = wr0[k] + vr[k];
            e0[k] = ex2f(fmaxf(a, 0.2f*a));
            z0 += e0[k];
            float c = wr1[k] + vr[k];
            e1[k] = ex2f(fmaxf(c, 0.2f*c));
            z1 += e1[k];
        }
        z0 += __shfl_xor_sync(m, z0, 16);  z1 += __shfl_xor_sync(m, z1, 16);
        z0 += __shfl_xor_sync(m, z0, 8);   z1 += __shfl_xor_sync(m, z1, 8);
        z0 += __shfl_xor_sync(m, z0, 4);   z1 += __shfl_xor_sync(m, z1, 4);
        z0 += __shfl_xor_sync(m, z0, 2);   z1 += __shfl_xor_sync(m, z1, 2);
        z0 += __shfl_xor_sync(m, z0, 1);   z1 += __shfl_xor_sync(m, z1, 1);
        float iz0 = (z0 > 0.f) ? rcpf(z0) : 0.f;
        float iz1 = (z1 > 0.f) ? rcpf(z1) : 0.f;
        #pragma unroll
        for (int k = 0; k < 6; ++k){
            acc0[k] += e0[k]*iz0;
            acc1[k] += e1[k]*iz1;
        }
    }

    #pragma unroll
    for (int k = 0; k < 4; ++k){
        AL[wp][0][4*lane+k] = acc0[k];
        AL[wp][1][4*lane+k] = acc1[k];
    }
    AL[wp][0][128+2*lane]   = acc0[4];
    AL[wp][0][128+2*lane+1] = acc0[5];
    AL[wp][1][128+2*lane]   = acc1[4];
    AL[wp][1][128+2*lane+1] = acc1[5];
    __syncthreads();
    w0[t] = ((AL[0][0][t]+AL[1][0][t]) + (AL[2][0][t]+AL[3][0][t])) + (AL[4][0][t]+AL[5][0][t]);
    w1[t] = ((AL[0][1][t]+AL[1][1][t]) + (AL[2][1][t]+AL[3][1][t])) + (AL[4][1][t]+AL[5][1][t]);
    __syncthreads();

    for (int idx = t; idx < 2*D_*(S_/4); idx += 192){
        int ii = idx / (D_*(S_/4));
        int r  = idx % (D_*(S_/4));
        int d  = r / (S_/4);
        int s4 = r % (S_/4);
        const float* ALp = ii ? w1 : w0;
        float4 a4 = *(const float4*)(ALp + s4*4);
        float sv = sg[d];
        float4 o = make_float4(a4.x*sv, a4.y*sv, a4.z*sv, a4.w*sv);
        *(float4*)(out + ((size_t)(b*HD_ + h*D_ + d)*N_ + i0 + ii)*S_ + s4*4) = o;
    }
}

extern "C" void kernel_launch(void* const* d_in, const int* in_sizes, int n_in,
                              void* d_out, int out_size){
    const float* X  = (const float*)d_in[0];
    const int*   A  = (const int*)  d_in[1];
    const float* Wl = (const float*)d_in[2];
    const float* bl = (const float*)d_in[3];
    const float* Wa = (const float*)d_in[4];
    const float* ba = (const float*)d_in[5];
    float* out = (float*)d_out;

    k_colsum<<<512, 256>>>(X);
    k_prep  <<<4, 128>>>(Wl, bl, Wa, ba);
    k_proj  <<<B_*N_*2, 384>>>(X, A);
    dim3 g(N_/2, H_, B_);
    k_attn  <<<g, 192>>>(Wl, bl, out);
}

// round 11
// speedup vs baseline: 1.2480x; 1.0452x over previous
#include <cuda_runtime.h>

#define B_ 2
#define F_ 128
#define N_ 192
#define S_ 192
#define H_ 4
#define D_ 64
#define HD_ 256
#define LOG2E 1.4426950408889634f

// SS[bh][i][s] = log2e*(s_src + q_src + b_attn), masked to -1e30 where A[s,i]==0
// SDT[bh][j][s] = log2e*(s_dst + q_dst)   (j-major for coalesced column reads)
static __device__ __align__(16) float d_SS [B_*H_*N_*S_];
static __device__ __align__(16) float d_SDT[B_*H_*N_*S_];
static __device__ float d_P[F_*8];
static __device__ float d_Q[8];
static __device__ float d_colsum2[B_*F_*2];
static __device__ float d_sumg[HD_];

__device__ __forceinline__ float ex2f(float x){ float r; asm("ex2.approx.ftz.f32 %0, %1;" : "=f"(r) : "f"(x)); return r; }
__device__ __forceinline__ float rcpf(float x){ float r; asm("rcp.approx.ftz.f32 %0, %1;" : "=f"(r) : "f"(x)); return r; }

// ---- launch 1: colsum half-slices ----
__global__ void __launch_bounds__(256) k_colsum(const float* __restrict__ X){
    int cb   = blockIdx.x;            // 512 half-slices
    int bf   = cb >> 1;
    int half = cb & 1;
    const float4* p = (const float4*)(X + (size_t)bf*(N_*S_) + half*(N_*S_/2));
    float acc = 0.f;
    #pragma unroll 6
    for (int i = threadIdx.x; i < (N_*S_)/8; i += 256){
        float4 v = __ldg(p + i);
        acc += (v.x + v.y) + (v.z + v.w);
    }
    unsigned m = 0xFFFFFFFFu;
    acc += __shfl_down_sync(m, acc, 16);
    acc += __shfl_down_sync(m, acc, 8);
    acc += __shfl_down_sync(m, acc, 4);
    acc += __shfl_down_sync(m, acc, 2);
    acc += __shfl_down_sync(m, acc, 1);
    __shared__ float wparts[8];
    if ((threadIdx.x & 31) == 0) wparts[threadIdx.x >> 5] = acc;
    __syncthreads();
    if (threadIdx.x == 0){
        float s = 0.f;
        #pragma unroll
        for (int k = 0; k < 8; ++k) s += wparts[k];
        d_colsum2[cb] = s;
    }
}

// ---- launch 2: blocks 0-3 fold W_attn into W_lin/b_lin; block 4 computes sum_g ----
__global__ void __launch_bounds__(256) k_prep(const float* __restrict__ Wl, const float* __restrict__ bl,
                                              const float* __restrict__ Wa, const float* __restrict__ ba){
    int t = threadIdx.x;
    if (blockIdx.x == 4){
        // sum_g[c] = colsumX · W_lin[:,c] + R*b_lin[c]
        __shared__ float cs[F_];
        if (t < F_)
            cs[t] = (d_colsum2[2*t] + d_colsum2[2*t+1])
                  + (d_colsum2[2*F_ + 2*t] + d_colsum2[2*F_ + 2*t+1]);
        __syncthreads();
        float acc = (float)(B_*N_*S_) * __ldg(bl + t);
        #pragma unroll
        for (int f0 = 0; f0 < F_; f0 += 16){
            float wv[16];
            #pragma unroll
            for (int k = 0; k < 16; ++k) wv[k] = __ldg(Wl + (f0+k)*HD_ + t);
            #pragma unroll
            for (int k = 0; k < 16; ++k) acc += cs[f0+k] * wv[k];
        }
        d_sumg[t] = acc;
        return;
    }
    if (t < 128){
        int f = blockIdx.x*32 + (t >> 2), h = t & 3;
        float ps = 0.f, pd = 0.f;
        #pragma unroll 8
        for (int d = 0; d < D_; ++d){
            float wl = Wl[f*HD_ + h*D_ + d];
            ps += wl * Wa[d];
            pd += wl * Wa[D_ + d];
        }
        d_P[f*8 + h]     = ps * LOG2E;
        d_P[f*8 + 4 + h] = pd * LOG2E;
    }
    if (blockIdx.x == 0 && t < 8){
        int which = t >> 2, hh = t & 3;
        float q = 0.f;
        for (int d = 0; d < D_; ++d) q += bl[hh*D_ + d] * Wa[which*D_ + d];
        if (which == 0) q += ba[0];
        d_Q[which*4 + hh] = q * LOG2E;
    }
}

// ---- launch 3: projection; block = (b, n, s-half), 4 f-quarter groups x 96 s ----
__global__ void __launch_bounds__(384, 4) k_proj(const float* __restrict__ X,
                                                 const int* __restrict__ A){
    __shared__ float sP[F_*8];
    __shared__ float sQ[8];
    __shared__ float pacc[3][96][9];
    int blk = blockIdx.x;
    int b  = blk / (N_*2);
    int r  = blk % (N_*2);
    int n  = r >> 1;
    int sh = r & 1;
    int t  = threadIdx.x;
    for (int i = t; i < F_*8; i += 384) sP[i] = d_P[i];
    if (t < 8) sQ[t] = d_Q[t];
    __syncthreads();
    int sl = t % 96;
    int fg = t / 96;
    int s  = sh*96 + sl;
    int fb = fg*32;
    float acc[8];
    #pragma unroll
    for (int k = 0; k < 8; ++k) acc[k] = 0.f;
    const float* xp = X + ((size_t)(b*F_ + fb)*N_ + n)*S_ + s;
    #pragma unroll
    for (int f0 = 0; f0 < 32; f0 += 16){
        float xv[16];
        #pragma unroll
        for (int k = 0; k < 16; ++k) xv[k] = __ldg(xp + (size_t)(f0+k)*(N_*S_));
        #pragma unroll
        for (int k = 0; k < 16; ++k){
            const float* pr = sP + (fb+f0+k)*8;
            float4 p0 = *(const float4*)pr;
            float4 p1 = *(const float4*)(pr+4);
            acc[0] += xv[k]*p0.x; acc[1] += xv[k]*p0.y; acc[2] += xv[k]*p0.z; acc[3] += xv[k]*p0.w;
            acc[4] += xv[k]*p1.x; acc[5] += xv[k]*p1.y; acc[6] += xv[k]*p1.z; acc[7] += xv[k]*p1.w;
        }
    }
    if (fg > 0){
        #pragma unroll
        for (int k = 0; k < 8; ++k) pacc[fg-1][sl][k] = acc[k];
    }
    __syncthreads();
    if (fg == 0){
        #pragma unroll
        for (int g = 0; g < 3; ++g)
            #pragma unroll
            for (int k = 0; k < 8; ++k) acc[k] += pacc[g][sl][k];
        int av = A[s*N_ + n];   // mask A[s, i=n]
        #pragma unroll
        for (int h = 0; h < H_; ++h){
            int bh = b*H_ + h;
            float u = acc[h] + sQ[h];
            d_SS [((size_t)bh*N_ + n)*S_ + s] = av ? u : -1e30f;
            d_SDT[((size_t)bh*N_ + n)*S_ + s] = acc[4+h] + sQ[4+h];
        }
    }
}

// ---- launch 4: attention; CTA per (b,h,i-pair); warp = 1 column/iter,
//      lanes 0-15 -> i0, lanes 16-31 -> i1, each lane owns 12 contiguous s ----
__global__ void __launch_bounds__(192, 6) k_attn(float* __restrict__ out){
    __shared__ float w0[S_], w1[S_];
    __shared__ float AL[6][2][S_];
    __shared__ float sg[D_];

    int i0 = blockIdx.x * 2, h = blockIdx.y, b = blockIdx.z;
    int bh = b*H_ + h;
    int t  = threadIdx.x, lane = t & 31, wp = t >> 5;
    int half = lane >> 4, hl = lane & 15;

    w0[t] = d_SS[((size_t)bh*N_ + i0    )*S_ + t];
    w1[t] = d_SS[((size_t)bh*N_ + i0 + 1)*S_ + t];
    if (t < D_) sg[t] = d_sumg[h*D_ + t];
    __syncthreads();

    // lane's 12 w values (contiguous s range)
    float wr[12], acc[12];
    {
        const float* wsrc = half ? w1 : w0;
        #pragma unroll
        for (int q = 0; q < 3; ++q){
            float4 v = *(const float4*)(wsrc + hl*12 + q*4);
            wr[q*4+0] = v.x; wr[q*4+1] = v.y; wr[q*4+2] = v.z; wr[q*4+3] = v.w;
        }
    }
    #pragma unroll
    for (int k = 0; k < 12; ++k) acc[k] = 0.f;

    const float* VT = d_SDT + (size_t)bh*N_*S_;
    const unsigned m = 0xFFFFFFFFu;

    for (int jj = 0; jj < 32; ++jj){
        const float* vrow = VT + (size_t)(wp*32 + jj)*S_ + hl*12;
        float4 va = __ldg((const float4*)(vrow    ));
        float4 vb = __ldg((const float4*)(vrow + 4));
        float4 vc = __ldg((const float4*)(vrow + 8));
        float vr[12] = {va.x,va.y,va.z,va.w, vb.x,vb.y,vb.z,vb.w, vc.x,vc.y,vc.z,vc.w};
        float e[12];
        float z = 0.f;
        #pragma unroll
        for (int k = 0; k < 12; ++k){
            float a = wr[k] + vr[k];
            e[k] = ex2f(fmaxf(a, 0.2f*a));
            z += e[k];
        }
        // 4-step reduction within each 16-lane half (both i's in the same 4 instr)
        z += __shfl_xor_sync(m, z, 8);
        z += __shfl_xor_sync(m, z, 4);
        z += __shfl_xor_sync(m, z, 2);
        z += __shfl_xor_sync(m, z, 1);
        float iz = rcpf(z + 1e-30f);   // all-masked column: e==0 -> 0*big = 0
        #pragma unroll
        for (int k = 0; k < 12; ++k) acc[k] += e[k]*iz;
    }

    // per-warp alpha partials (lane's contiguous 12-s range of its i)
    {
        float* dst = &AL[wp][half][hl*12];
        *(float4*)(dst    ) = make_float4(acc[0], acc[1], acc[2],  acc[3]);
        *(float4*)(dst + 4) = make_float4(acc[4], acc[5], acc[6],  acc[7]);
        *(float4*)(dst + 8) = make_float4(acc[8], acc[9], acc[10], acc[11]);
    }
    __syncthreads();
    w0[t] = ((AL[0][0][t]+AL[1][0][t]) + (AL[2][0][t]+AL[3][0][t])) + (AL[4][0][t]+AL[5][0][t]);
    w1[t] = ((AL[0][1][t]+AL[1][1][t]) + (AL[2][1][t]+AL[3][1][t])) + (AL[4][1][t]+AL[5][1][t]);
    __syncthreads();

    for (int idx = t; idx < 2*D_*(S_/4); idx += 192){
        int ii = idx / (D_*(S_/4));
        int r  = idx % (D_*(S_/4));
        int d  = r / (S_/4);
        int s4 = r % (S_/4);
        const float* ALp = ii ? w1 : w0;
        float4 a4 = *(const float4*)(ALp + s4*4);
        float sv = sg[d];
        float4 o = make_float4(a4.x*sv, a4.y*sv, a4.z*sv, a4.w*sv);
        *(float4*)(out + ((size_t)(b*HD_ + h*D_ + d)*N_ + i0 + ii)*S_ + s4*4) = o;
    }
}

extern "C" void kernel_launch(void* const* d_in, const int* in_sizes, int n_in,
                              void* d_out, int out_size){
    const float* X  = (const float*)d_in[0];
    const int*   A  = (const int*)  d_in[1];
    const float* Wl = (const float*)d_in[2];
    const float* bl = (const float*)d_in[3];
    const float* Wa = (const float*)d_in[4];
    const float* ba = (const float*)d_in[5];
    float* out = (float*)d_out;

    k_colsum<<<512, 256>>>(X);
    k_prep  <<<5, 256>>>(Wl, bl, Wa, ba);
    k_proj  <<<B_*N_*2, 384>>>(X, A);
    dim3 g(N_/2, H_, B_);
    k_attn  <<<g, 192>>>(out);
}